// round 9
// baseline (speedup 1.0000x reference)
#include <cuda_runtime.h>
#include <cuda_bf16.h>
#include <math.h>

#define B_  2
#define C_  32
#define S_  (24*64*128)               /* 196608 positions per batch */
#define NTOT ((size_t)C_*(size_t)S_)  /* 6291456 elems per batch */
#define NS_  256
#define FC_  256
#define NRED 576                      /* stage-1 reduce blocks per batch */

/* ===================== persistent device scratch ========================== */
__device__ double g_p1s[B_][NRED], g_p1q[B_][NRED];   /* stage-1 partials */
__device__ double g_s2[B_], g_q2[B_];                 /* stage-2 accumulators */
__device__ float  g_qb[B_][C_];
__device__ __align__(16) __nv_bfloat16 g_Kb[B_][2][256][16];  /* pre-scaled K */
__device__ __align__(16) __nv_bfloat16 g_Vt[B_][2][16][256];  /* V transposed */
__device__ __align__(16) __nv_bfloat16 g_Wqb[B_][32][32];     /* GN-folded */
__device__ __align__(16) __nv_bfloat16 g_Wob[32][32];

/* ===================== helpers ============================================ */
__device__ __forceinline__ float fexp(float x) {   /* Schraudolph, ~2% max rel err */
    return __int_as_float(__float2int_rn(fmaf(x, 12102203.0f, 1064866805.0f)));
}
__device__ __forceinline__ unsigned packbf(float lo, float hi) {
    __nv_bfloat162 h2 = __floats2bfloat162_rn(lo, hi);
    return *(unsigned*)&h2;
}
/* D += A(16x16 bf16,row) * B(16x8 bf16,col) ; f32 accum */
__device__ __forceinline__ void mma16816(float* d, const unsigned* a, const unsigned* b) {
    asm volatile("mma.sync.aligned.m16n8k16.row.col.f32.bf16.bf16.f32 "
        "{%0,%1,%2,%3}, {%4,%5,%6,%7}, {%8,%9}, {%0,%1,%2,%3};"
        : "+f"(d[0]), "+f"(d[1]), "+f"(d[2]), "+f"(d[3])
        : "r"(a[0]), "r"(a[1]), "r"(a[2]), "r"(a[3]), "r"(b[0]), "r"(b[1]));
}

/* ===================== K1: prep (KV projection + wide stage-1 stats) ====== */
__global__ void k_prep(const float* __restrict__ feat,
                       const float* __restrict__ Wk,
                       const float* __restrict__ Wv,
                       const float* __restrict__ cost) {
    const int bx = blockIdx.x, b = blockIdx.y, t = threadIdx.x;
    if (bx < 64) {                       /* ---- KV role ---- */
        __shared__ float sf[4][FC_];
        int g = t >> 6, u = t & 63;
        int n = bx * 4 + g;
        for (int i = u; i < FC_; i += 64)
            sf[g][i] = feat[((size_t)b * FC_ + i) * NS_ + n];
        __syncthreads();
        const float* Wr = (u < 32) ? (Wk + (size_t)u * FC_)
                                   : (Wv + (size_t)(u - 32) * FC_);
        const float4* W4 = (const float4*)Wr;
        const float4* f4 = (const float4*)sf[g];
        float acc = 0.f;
        #pragma unroll 8
        for (int i = 0; i < FC_ / 4; i++) {
            float4 w = W4[i]; float4 f = f4[i];
            acc += w.x*f.x + w.y*f.y + w.z*f.z + w.w*f.w;
        }
        if (u < 32) g_Kb[b][u >> 4][n][u & 15] = __float2bfloat16(acc * 0.25f);
        else { int v = u - 32; g_Vt[b][v >> 4][v & 15][n] = __float2bfloat16(acc); }
    } else {                             /* ---- stage-1 stats role ---- */
        const int r = bx - 64;
        const float4* p = (const float4*)(cost + (size_t)b * NTOT);
        const int n4 = (int)(NTOT / 4);
        const int stride = NRED * 256;
        float s0 = 0.f, s1 = 0.f, q0 = 0.f, q1 = 0.f;
        int i = r * 256 + t;
        for (; i + 3 * stride < n4; i += 4 * stride) {
            float4 a = p[i], bv = p[i + stride], c = p[i + 2*stride], d = p[i + 3*stride];
            s0 += (a.x + a.y) + (a.z + a.w);
            q0 += (a.x*a.x + a.y*a.y) + (a.z*a.z + a.w*a.w);
            s1 += (bv.x + bv.y) + (bv.z + bv.w);
            q1 += (bv.x*bv.x + bv.y*bv.y) + (bv.z*bv.z + bv.w*bv.w);
            s0 += (c.x + c.y) + (c.z + c.w);
            q0 += (c.x*c.x + c.y*c.y) + (c.z*c.z + c.w*c.w);
            s1 += (d.x + d.y) + (d.z + d.w);
            q1 += (d.x*d.x + d.y*d.y) + (d.z*d.z + d.w*d.w);
        }
        for (; i < n4; i += stride) {
            float4 a = p[i];
            s0 += (a.x + a.y) + (a.z + a.w);
            q0 += (a.x*a.x + a.y*a.y) + (a.z*a.z + a.w*a.w);
        }
        float s = s0 + s1, q = q0 + q1;
        #pragma unroll
        for (int o = 16; o; o >>= 1) {
            s += __shfl_down_sync(0xffffffffu, s, o);
            q += __shfl_down_sync(0xffffffffu, q, o);
        }
        __shared__ float ss[8], sq[8];
        int lane = t & 31, w = t >> 5;
        if (lane == 0) { ss[w] = s; sq[w] = q; }
        __syncthreads();
        if (t == 0) {
            float ts = 0.f, tq = 0.f;
            #pragma unroll
            for (int i2 = 0; i2 < 8; i2++) { ts += ss[i2]; tq += sq[i2]; }
            g_p1s[b][r] = (double)ts;
            g_p1q[b][r] = (double)tq;
        }
    }
}

/* ===================== K2: fold stats into GN-folded weights ============== */
__global__ void k_fold(const float* __restrict__ Wq, const float* __restrict__ Wo,
                       const float* __restrict__ gw, const float* __restrict__ gb) {
    const int b = blockIdx.x, t = threadIdx.x;
    __shared__ float smi[2];
    {
        double s = 0.0, q = 0.0;
        for (int i = t; i < NRED; i += 1024) { s += g_p1s[b][i]; q += g_p1q[b][i]; }
        #pragma unroll
        for (int o = 16; o; o >>= 1) {
            s += __shfl_down_sync(0xffffffffu, s, o);
            q += __shfl_down_sync(0xffffffffu, q, o);
        }
        __shared__ double ds[32], dq[32];
        int lane = t & 31, w = t >> 5;
        if (lane == 0) { ds[w] = s; dq[w] = q; }
        __syncthreads();
        if (t == 0) {
            double ts = 0.0, tq = 0.0;
            #pragma unroll
            for (int i = 0; i < 32; i++) { ts += ds[i]; tq += dq[i]; }
            double mean = ts / (double)NTOT;
            double var  = tq / (double)NTOT - mean * mean;
            smi[0] = (float)mean;
            smi[1] = (float)(1.0 / sqrt(var + 1e-5));
            g_s2[b] = 0.0; g_q2[b] = 0.0;
        }
        __syncthreads();
    }
    const float mu = smi[0], inv = smi[1];
    int o = t >> 5, c = t & 31;
    g_Wqb[b][o][c] = __float2bfloat16(Wq[o * C_ + c] * gw[c] * inv);
    if (b == 0) g_Wob[o][c] = __float2bfloat16(Wo[o * C_ + c]);
    if (t < C_) {
        float acc = 0.f;
        for (int cc = 0; cc < C_; cc++)
            acc += Wq[t * C_ + cc] * (gb[cc] - gw[cc] * mu * inv);
        g_qb[b][t] = acc;
    }
}

/* ===================== K3: mma.sync flash attention ======================= */
#define SM_K   0
#define SM_V   24576
#define SM_WQ  41472
#define SM_WO  44032
#define SM_QB  46592
#define SM_RED 46720
#define SM_BYTES 46784

__global__ void __launch_bounds__(128, 4)
k_attn_mma(const float* __restrict__ cost, const float* __restrict__ gammap,
           float* __restrict__ y) {
    __shared__ __align__(16) unsigned char sm[SM_BYTES];
    const int tid = threadIdx.x;
    const int w = tid >> 5, lane = tid & 31;
    const int gid = lane >> 2, tig = lane & 3;
    const int b = blockIdx.y;

    {   /* cooperative smem fill from staged global tiles */
        const uint4* srcK = (const uint4*)&g_Kb[b][0][0][0];   /* 512 rows x 32B */
        for (int i = tid; i < 1024; i += 128)
            *(uint4*)(sm + SM_K + (i >> 1) * 48 + (i & 1) * 16) = srcK[i];
        const uint4* srcV = (const uint4*)&g_Vt[b][0][0][0];   /* 32 rows x 512B */
        for (int i = tid; i < 1024; i += 128)
            *(uint4*)(sm + SM_V + (i >> 5) * 528 + (i & 31) * 16) = srcV[i];
        const uint4* srcQ = (const uint4*)&g_Wqb[b][0][0];     /* 32 rows x 64B */
        for (int i = tid; i < 128; i += 128)
            *(uint4*)(sm + SM_WQ + (i >> 2) * 80 + (i & 3) * 16) = srcQ[i];
        const uint4* srcO = (const uint4*)&g_Wob[0][0];
        for (int i = tid; i < 128; i += 128)
            *(uint4*)(sm + SM_WO + (i >> 2) * 80 + (i & 3) * 16) = srcO[i];
        if (tid < 32) ((float*)(sm + SM_QB))[tid] = g_qb[b][tid];
    }
    __syncthreads();

    const int pos0 = blockIdx.x * 128;
    const int rabs[2] = { pos0 + w * 32 + gid, pos0 + w * 32 + 16 + gid };
    const float* xb = cost + (size_t)b * NTOT;
    const float* sqbf = (const float*)(sm + SM_QB);

    /* ---- Phase A: Qproj  Q = X @ Wq_eff^T + qb ---- */
    unsigned qf[2][2][4];   /* [head][mtile][4] A-fragments of Q (bf16) */
    {
        unsigned xa[2][2][4];
        #pragma unroll
        for (int mt = 0; mt < 2; mt++) {
            int r0 = rabs[mt], r1 = r0 + 8;
            #pragma unroll
            for (int kt = 0; kt < 2; kt++) {
                int c = kt * 16 + tig * 2;
                xa[mt][kt][0] = packbf(xb[(size_t)c*S_ + r0],     xb[(size_t)(c+1)*S_ + r0]);
                xa[mt][kt][1] = packbf(xb[(size_t)c*S_ + r1],     xb[(size_t)(c+1)*S_ + r1]);
                xa[mt][kt][2] = packbf(xb[(size_t)(c+8)*S_ + r0], xb[(size_t)(c+9)*S_ + r0]);
                xa[mt][kt][3] = packbf(xb[(size_t)(c+8)*S_ + r1], xb[(size_t)(c+9)*S_ + r1]);
            }
        }
        float qc[2][4][4];
        #pragma unroll
        for (int mt = 0; mt < 2; mt++)
            #pragma unroll
            for (int nt = 0; nt < 4; nt++)
                #pragma unroll
                for (int j = 0; j < 4; j++) qc[mt][nt][j] = 0.f;
        #pragma unroll
        for (int nt = 0; nt < 4; nt++) {
            const unsigned char* Wr = sm + SM_WQ + (nt * 8 + gid) * 80;
            unsigned bq[2][2];
            bq[0][0] = *(const unsigned*)(Wr + tig * 4);
            bq[0][1] = *(const unsigned*)(Wr + 16 + tig * 4);
            bq[1][0] = *(const unsigned*)(Wr + 32 + tig * 4);
            bq[1][1] = *(const unsigned*)(Wr + 48 + tig * 4);
            #pragma unroll
            for (int mt = 0; mt < 2; mt++) {
                mma16816(qc[mt][nt], xa[mt][0], bq[0]);
                mma16816(qc[mt][nt], xa[mt][1], bq[1]);
            }
            float b0 = sqbf[nt * 8 + tig * 2], b1 = sqbf[nt * 8 + tig * 2 + 1];
            #pragma unroll
            for (int mt = 0; mt < 2; mt++) {
                qc[mt][nt][0] += b0; qc[mt][nt][1] += b1;
                qc[mt][nt][2] += b0; qc[mt][nt][3] += b1;
            }
        }
        #pragma unroll
        for (int h = 0; h < 2; h++)
            #pragma unroll
            for (int mt = 0; mt < 2; mt++) {
                qf[h][mt][0] = packbf(qc[mt][2*h][0],   qc[mt][2*h][1]);
                qf[h][mt][1] = packbf(qc[mt][2*h][2],   qc[mt][2*h][3]);
                qf[h][mt][2] = packbf(qc[mt][2*h+1][0], qc[mt][2*h+1][1]);
                qf[h][mt][3] = packbf(qc[mt][2*h+1][2], qc[mt][2*h+1][3]);
            }
    }

    /* ---- Phase B: head-interleaved streaming softmax-attention ----
       h0/h1 chains are independent -> 2x ILP across the mma->exp->mma
       dependency. Per-head accumulation order identical to R4/R8.     */
    unsigned zf[2][2][4];   /* [mtile][ktile=head] Z A-fragments */
    {
        float oa[2][2][2][4];     /* [h][mt][dt][j] */
        float s0[2][2], s1[2][2]; /* [h][mt] */
        #pragma unroll
        for (int h = 0; h < 2; h++)
            #pragma unroll
            for (int mt = 0; mt < 2; mt++) {
                s0[h][mt] = 0.f; s1[h][mt] = 0.f;
                #pragma unroll
                for (int dt = 0; dt < 2; dt++)
                    #pragma unroll
                    for (int j = 0; j < 4; j++) oa[h][mt][dt][j] = 0.f;
            }
        #pragma unroll 2
        for (int nt2 = 0; nt2 < 16; nt2++) {
            const int t0 = nt2 * 16;
            #pragma unroll
            for (int h = 0; h < 2; h++) {
                const unsigned char* Kh = sm + SM_K + h * 12288;
                const unsigned char* Vh = sm + SM_V + h * 8448;
                unsigned kb[2][2], vb[2][2];
                kb[0][0] = *(const unsigned*)(Kh + (t0 + gid) * 48 + tig * 4);
                kb[0][1] = *(const unsigned*)(Kh + (t0 + gid) * 48 + 16 + tig * 4);
                kb[1][0] = *(const unsigned*)(Kh + (t0 + 8 + gid) * 48 + tig * 4);
                kb[1][1] = *(const unsigned*)(Kh + (t0 + 8 + gid) * 48 + 16 + tig * 4);
                vb[0][0] = *(const unsigned*)(Vh + gid * 528 + t0 * 2 + tig * 4);
                vb[0][1] = *(const unsigned*)(Vh + gid * 528 + t0 * 2 + 16 + tig * 4);
                vb[1][0] = *(const unsigned*)(Vh + (8 + gid) * 528 + t0 * 2 + tig * 4);
                vb[1][1] = *(const unsigned*)(Vh + (8 + gid) * 528 + t0 * 2 + 16 + tig * 4);
                #pragma unroll
                for (int mt = 0; mt < 2; mt++) {
                    float sc0[4] = {0.f,0.f,0.f,0.f}, sc1[4] = {0.f,0.f,0.f,0.f};
                    mma16816(sc0, qf[h][mt], kb[0]);
                    mma16816(sc1, qf[h][mt], kb[1]);
                    float e0 = fexp(sc0[0]), e1 = fexp(sc0[1]);
                    float e2 = fexp(sc0[2]), e3 = fexp(sc0[3]);
                    float f0 = fexp(sc1[0]), f1 = fexp(sc1[1]);
                    float f2 = fexp(sc1[2]), f3 = fexp(sc1[3]);
                    s0[h][mt] += (e0 + e1) + (f0 + f1);
                    s1[h][mt] += (e2 + e3) + (f2 + f3);
                    unsigned pa[4] = { packbf(e0, e1), packbf(e2, e3),
                                       packbf(f0, f1), packbf(f2, f3) };
                    mma16816(oa[h][mt][0], pa, vb[0]);
                    mma16816(oa[h][mt][1], pa, vb[1]);
                }
            }
        }
        #pragma unroll
        for (int h = 0; h < 2; h++)
            #pragma unroll
            for (int mt = 0; mt < 2; mt++) {
                float a0 = s0[h][mt], a1 = s1[h][mt];
                a0 += __shfl_xor_sync(0xffffffffu, a0, 1);
                a0 += __shfl_xor_sync(0xffffffffu, a0, 2);
                a1 += __shfl_xor_sync(0xffffffffu, a1, 1);
                a1 += __shfl_xor_sync(0xffffffffu, a1, 2);
                float i0 = 1.f / a0, i1 = 1.f / a1;
                zf[mt][h][0] = packbf(oa[h][mt][0][0] * i0, oa[h][mt][0][1] * i0);
                zf[mt][h][1] = packbf(oa[h][mt][0][2] * i1, oa[h][mt][0][3] * i1);
                zf[mt][h][2] = packbf(oa[h][mt][1][0] * i0, oa[h][mt][1][1] * i0);
                zf[mt][h][3] = packbf(oa[h][mt][1][2] * i1, oa[h][mt][1][3] * i1);
            }
    }

    /* ---- Phase C: Y = Z @ Wo^T ; residual, write, output-GN stats ---- */
    float gam = __ldg(gammap);
    float lsum = 0.f, lsq = 0.f;
    float* yb = y + (size_t)b * NTOT;
    #pragma unroll
    for (int nt = 0; nt < 4; nt++) {
        const unsigned char* Wr = sm + SM_WO + (nt * 8 + gid) * 80;
        unsigned bo[2][2];
        bo[0][0] = *(const unsigned*)(Wr + tig * 4);
        bo[0][1] = *(const unsigned*)(Wr + 16 + tig * 4);
        bo[1][0] = *(const unsigned*)(Wr + 32 + tig * 4);
        bo[1][1] = *(const unsigned*)(Wr + 48 + tig * 4);
        #pragma unroll
        for (int mt = 0; mt < 2; mt++) {
            float yc[4] = {0.f, 0.f, 0.f, 0.f};
            mma16816(yc, zf[mt][0], bo[0]);
            mma16816(yc, zf[mt][1], bo[1]);
            int ch = nt * 8 + tig * 2;
            int r0 = rabs[mt];
            size_t i00 = (size_t)ch * S_ + r0;
            size_t i01 = i00 + S_;
            float y00 = xb[i00]     + gam * yc[0];
            float y01 = xb[i01]     + gam * yc[1];
            float y10 = xb[i00 + 8] + gam * yc[2];
            float y11 = xb[i01 + 8] + gam * yc[3];
            yb[i00] = y00; yb[i01] = y01; yb[i00 + 8] = y10; yb[i01 + 8] = y11;
            lsum += (y00 + y01) + (y10 + y11);
            lsq  += (y00*y00 + y01*y01) + (y10*y10 + y11*y11);
        }
    }
    #pragma unroll
    for (int o = 16; o; o >>= 1) {
        lsum += __shfl_down_sync(0xffffffffu, lsum, o);
        lsq  += __shfl_down_sync(0xffffffffu, lsq,  o);
    }
    float* red = (float*)(sm + SM_RED);
    __syncthreads();
    if (lane == 0) { red[w] = lsum; red[4 + w] = lsq; }
    __syncthreads();
    if (tid == 0) {
        float ts = red[0] + red[1] + red[2] + red[3];
        float tq = red[4] + red[5] + red[6] + red[7];
        atomicAdd(&g_s2[b], (double)ts);
        atomicAdd(&g_q2[b], (double)tq);
    }
}

/* ===================== K4: output GroupNorm (exact-cover, MLP=4) ========== */
/* grid (48, B_*C_), block 256: thread j handles 4 independent float4 at
   stride 12288; 48*256*4 = 49152 = S_/4 exactly — no loop, no tail.        */
__global__ void k_final(float* __restrict__ out,
                        const float* __restrict__ gw, const float* __restrict__ gb) {
    int bc = blockIdx.y;
    int b = bc >> 5, c = bc & 31;
    double mean = g_s2[b] / (double)NTOT;
    double var  = g_q2[b] / (double)NTOT - mean * mean;
    float inv = (float)(1.0 / sqrt(var + 1e-5));
    float a  = gw[c] * inv;
    float bb = gb[c] - gw[c] * (float)mean * inv;
    float4* p = (float4*)(out + ((size_t)b * C_ + c) * S_);
    int j = blockIdx.x * 256 + threadIdx.x;     /* 0..12287 */
    float4 v0 = p[j], v1 = p[j + 12288], v2 = p[j + 24576], v3 = p[j + 36864];
    v0.x = a*v0.x + bb; v0.y = a*v0.y + bb; v0.z = a*v0.z + bb; v0.w = a*v0.w + bb;
    v1.x = a*v1.x + bb; v1.y = a*v1.y + bb; v1.z = a*v1.z + bb; v1.w = a*v1.w + bb;
    v2.x = a*v2.x + bb; v2.y = a*v2.y + bb; v2.z = a*v2.z + bb; v2.w = a*v2.w + bb;
    v3.x = a*v3.x + bb; v3.y = a*v3.y + bb; v3.z = a*v3.z + bb; v3.w = a*v3.w + bb;
    p[j] = v0; p[j + 12288] = v1; p[j + 24576] = v2; p[j + 36864] = v3;
}

/* ===================== launch ============================================= */
extern "C" void kernel_launch(void* const* d_in, const int* in_sizes, int n_in,
                              void* d_out, int out_size) {
    const float* cost  = (const float*)d_in[0];
    const float* feat  = (const float*)d_in[1];
    const float* Wq    = (const float*)d_in[2];
    const float* Wk    = (const float*)d_in[3];
    const float* Wv    = (const float*)d_in[4];
    const float* Wo    = (const float*)d_in[5];
    const float* gniw  = (const float*)d_in[6];
    const float* gnib  = (const float*)d_in[7];
    const float* gnow  = (const float*)d_in[8];
    const float* gnob  = (const float*)d_in[9];
    const float* gamma = (const float*)d_in[10];
    float* out = (float*)d_out;

    k_prep<<<dim3(64 + NRED, B_), 256>>>(feat, Wk, Wv, cost);
    k_fold<<<B_, 1024>>>(Wq, Wo, gniw, gnib);
    k_attn_mma<<<dim3(S_ / 128, B_), 128>>>(cost, gamma, out);
    k_final<<<dim3(48, B_ * C_), 256>>>(out, gnow, gnob);
}

// round 10
// speedup vs baseline: 1.1841x; 1.1841x over previous
#include <cuda_runtime.h>
#include <cuda_bf16.h>
#include <math.h>

#define B_  2
#define C_  32
#define S_  (24*64*128)               /* 196608 positions per batch */
#define NTOT ((size_t)C_*(size_t)S_)  /* 6291456 elems per batch */
#define NS_  256
#define FC_  256
#define NRED 576                      /* stage-1 reduce blocks per batch */

/* ===================== persistent device scratch ========================== */
__device__ double g_p1s[B_][NRED], g_p1q[B_][NRED];   /* stage-1 partials */
__device__ double g_s2[B_], g_q2[B_];                 /* stage-2 accumulators */
__device__ float  g_qb[B_][C_];
__device__ __align__(16) __nv_bfloat16 g_Kb[B_][2][256][16];  /* pre-scaled K */
__device__ __align__(16) __nv_bfloat16 g_Vt[B_][2][16][256];  /* V transposed */
__device__ __align__(16) __nv_bfloat16 g_Wqb[B_][32][32];     /* GN-folded */
__device__ __align__(16) __nv_bfloat16 g_Wob[32][32];

/* ===================== helpers ============================================ */
__device__ __forceinline__ unsigned packbf(float lo, float hi) {
    __nv_bfloat162 h2 = __floats2bfloat162_rn(lo, hi);
    return *(unsigned*)&h2;
}
/* bf16 magic-exp: low 16 bits of z hold bf16(exp(x)) (Schraudolph @ bf16).
   Common scale 2^(-eps/128) from addend rounding cancels in softmax. */
#define FEA 184.6650f
#define FEB 12599160.33f   /* 1.5*2^23 + 1064866805/65536 */
__device__ __forceinline__ unsigned fexp2bf(float x0, float x1) {
    float z0 = fmaf(x0, FEA, FEB);
    float z1 = fmaf(x1, FEA, FEB);
    return __byte_perm(__float_as_uint(z0), __float_as_uint(z1), 0x5410);
}
/* D += A(16x16 bf16,row) * B(16x8 bf16,col) ; f32 accum */
__device__ __forceinline__ void mma16816(float* d, const unsigned* a, const unsigned* b) {
    asm volatile("mma.sync.aligned.m16n8k16.row.col.f32.bf16.bf16.f32 "
        "{%0,%1,%2,%3}, {%4,%5,%6,%7}, {%8,%9}, {%0,%1,%2,%3};"
        : "+f"(d[0]), "+f"(d[1]), "+f"(d[2]), "+f"(d[3])
        : "r"(a[0]), "r"(a[1]), "r"(a[2]), "r"(a[3]), "r"(b[0]), "r"(b[1]));
}

/* ===================== K1: prep (KV projection + wide stage-1 stats) ====== */
__global__ void k_prep(const float* __restrict__ feat,
                       const float* __restrict__ Wk,
                       const float* __restrict__ Wv,
                       const float* __restrict__ cost) {
    const int bx = blockIdx.x, b = blockIdx.y, t = threadIdx.x;
    if (bx < 64) {                       /* ---- KV role ---- */
        __shared__ float sf[4][FC_];
        int g = t >> 6, u = t & 63;
        int n = bx * 4 + g;
        for (int i = u; i < FC_; i += 64)
            sf[g][i] = feat[((size_t)b * FC_ + i) * NS_ + n];
        __syncthreads();
        const float* Wr = (u < 32) ? (Wk + (size_t)u * FC_)
                                   : (Wv + (size_t)(u - 32) * FC_);
        const float4* W4 = (const float4*)Wr;
        const float4* f4 = (const float4*)sf[g];
        float acc = 0.f;
        #pragma unroll 8
        for (int i = 0; i < FC_ / 4; i++) {
            float4 w = W4[i]; float4 f = f4[i];
            acc += w.x*f.x + w.y*f.y + w.z*f.z + w.w*f.w;
        }
        if (u < 32) g_Kb[b][u >> 4][n][u & 15] = __float2bfloat16(acc * 0.25f);
        else { int v = u - 32; g_Vt[b][v >> 4][v & 15][n] = __float2bfloat16(acc); }
    } else {                             /* ---- stage-1 stats role ---- */
        const int r = bx - 64;
        const float4* p = (const float4*)(cost + (size_t)b * NTOT);
        const int n4 = (int)(NTOT / 4);
        const int stride = NRED * 256;
        float s0 = 0.f, s1 = 0.f, q0 = 0.f, q1 = 0.f;
        int i = r * 256 + t;
        for (; i + 3 * stride < n4; i += 4 * stride) {
            float4 a = p[i], bv = p[i + stride], c = p[i + 2*stride], d = p[i + 3*stride];
            s0 += (a.x + a.y) + (a.z + a.w);
            q0 += (a.x*a.x + a.y*a.y) + (a.z*a.z + a.w*a.w);
            s1 += (bv.x + bv.y) + (bv.z + bv.w);
            q1 += (bv.x*bv.x + bv.y*bv.y) + (bv.z*bv.z + bv.w*bv.w);
            s0 += (c.x + c.y) + (c.z + c.w);
            q0 += (c.x*c.x + c.y*c.y) + (c.z*c.z + c.w*c.w);
            s1 += (d.x + d.y) + (d.z + d.w);
            q1 += (d.x*d.x + d.y*d.y) + (d.z*d.z + d.w*d.w);
        }
        for (; i < n4; i += stride) {
            float4 a = p[i];
            s0 += (a.x + a.y) + (a.z + a.w);
            q0 += (a.x*a.x + a.y*a.y) + (a.z*a.z + a.w*a.w);
        }
        float s = s0 + s1, q = q0 + q1;
        #pragma unroll
        for (int o = 16; o; o >>= 1) {
            s += __shfl_down_sync(0xffffffffu, s, o);
            q += __shfl_down_sync(0xffffffffu, q, o);
        }
        __shared__ float ss[8], sq[8];
        int lane = t & 31, w = t >> 5;
        if (lane == 0) { ss[w] = s; sq[w] = q; }
        __syncthreads();
        if (t == 0) {
            float ts = 0.f, tq = 0.f;
            #pragma unroll
            for (int i2 = 0; i2 < 8; i2++) { ts += ss[i2]; tq += sq[i2]; }
            g_p1s[b][r] = (double)ts;
            g_p1q[b][r] = (double)tq;
        }
    }
}

/* ===================== K2: fold stats into GN-folded weights ============== */
__global__ void k_fold(const float* __restrict__ Wq, const float* __restrict__ Wo,
                       const float* __restrict__ gw, const float* __restrict__ gb) {
    const int b = blockIdx.x, t = threadIdx.x;
    __shared__ float smi[2];
    {
        double s = 0.0, q = 0.0;
        for (int i = t; i < NRED; i += 1024) { s += g_p1s[b][i]; q += g_p1q[b][i]; }
        #pragma unroll
        for (int o = 16; o; o >>= 1) {
            s += __shfl_down_sync(0xffffffffu, s, o);
            q += __shfl_down_sync(0xffffffffu, q, o);
        }
        __shared__ double ds[32], dq[32];
        int lane = t & 31, w = t >> 5;
        if (lane == 0) { ds[w] = s; dq[w] = q; }
        __syncthreads();
        if (t == 0) {
            double ts = 0.0, tq = 0.0;
            #pragma unroll
            for (int i = 0; i < 32; i++) { ts += ds[i]; tq += dq[i]; }
            double mean = ts / (double)NTOT;
            double var  = tq / (double)NTOT - mean * mean;
            smi[0] = (float)mean;
            smi[1] = (float)(1.0 / sqrt(var + 1e-5));
            g_s2[b] = 0.0; g_q2[b] = 0.0;
        }
        __syncthreads();
    }
    const float mu = smi[0], inv = smi[1];
    int o = t >> 5, c = t & 31;
    g_Wqb[b][o][c] = __float2bfloat16(Wq[o * C_ + c] * gw[c] * inv);
    if (b == 0) g_Wob[o][c] = __float2bfloat16(Wo[o * C_ + c]);
    if (t < C_) {
        float acc = 0.f;
        for (int cc = 0; cc < C_; cc++)
            acc += Wq[t * C_ + cc] * (gb[cc] - gw[cc] * mu * inv);
        g_qb[b][t] = acc;
    }
}

/* ===================== K3: mma.sync flash attention ======================= */
#define SM_K   0
#define SM_V   24576
#define SM_WQ  41472
#define SM_WO  44032
#define SM_QB  46592
#define SM_RED 46720
#define SM_BYTES 46784

__global__ void __launch_bounds__(128, 4)
k_attn_mma(const float* __restrict__ cost, const float* __restrict__ gammap,
           float* __restrict__ y) {
    __shared__ __align__(16) unsigned char sm[SM_BYTES];
    const int tid = threadIdx.x;
    const int w = tid >> 5, lane = tid & 31;
    const int gid = lane >> 2, tig = lane & 3;
    const int b = blockIdx.y;

    {   /* cooperative smem fill from staged global tiles */
        const uint4* srcK = (const uint4*)&g_Kb[b][0][0][0];   /* 512 rows x 32B */
        for (int i = tid; i < 1024; i += 128)
            *(uint4*)(sm + SM_K + (i >> 1) * 48 + (i & 1) * 16) = srcK[i];
        const uint4* srcV = (const uint4*)&g_Vt[b][0][0][0];   /* 32 rows x 512B */
        for (int i = tid; i < 1024; i += 128)
            *(uint4*)(sm + SM_V + (i >> 5) * 528 + (i & 31) * 16) = srcV[i];
        const uint4* srcQ = (const uint4*)&g_Wqb[b][0][0];     /* 32 rows x 64B */
        for (int i = tid; i < 128; i += 128)
            *(uint4*)(sm + SM_WQ + (i >> 2) * 80 + (i & 3) * 16) = srcQ[i];
        const uint4* srcO = (const uint4*)&g_Wob[0][0];
        for (int i = tid; i < 128; i += 128)
            *(uint4*)(sm + SM_WO + (i >> 2) * 80 + (i & 3) * 16) = srcO[i];
        if (tid < 32) ((float*)(sm + SM_QB))[tid] = g_qb[b][tid];
    }
    __syncthreads();

    const int pos0 = blockIdx.x * 128;
    const int rabs[2] = { pos0 + w * 32 + gid, pos0 + w * 32 + 16 + gid };
    const float* xb = cost + (size_t)b * NTOT;
    const float* sqbf = (const float*)(sm + SM_QB);

    /* ---- Phase A: Qproj  Q = X @ Wq_eff^T + qb ---- */
    unsigned qf[2][2][4];   /* [head][mtile][4] A-fragments of Q (bf16) */
    {
        unsigned xa[2][2][4];
        #pragma unroll
        for (int mt = 0; mt < 2; mt++) {
            int r0 = rabs[mt], r1 = r0 + 8;
            #pragma unroll
            for (int kt = 0; kt < 2; kt++) {
                int c = kt * 16 + tig * 2;
                xa[mt][kt][0] = packbf(xb[(size_t)c*S_ + r0],     xb[(size_t)(c+1)*S_ + r0]);
                xa[mt][kt][1] = packbf(xb[(size_t)c*S_ + r1],     xb[(size_t)(c+1)*S_ + r1]);
                xa[mt][kt][2] = packbf(xb[(size_t)(c+8)*S_ + r0], xb[(size_t)(c+9)*S_ + r0]);
                xa[mt][kt][3] = packbf(xb[(size_t)(c+8)*S_ + r1], xb[(size_t)(c+9)*S_ + r1]);
            }
        }
        float qc[2][4][4];
        #pragma unroll
        for (int mt = 0; mt < 2; mt++)
            #pragma unroll
            for (int nt = 0; nt < 4; nt++)
                #pragma unroll
                for (int j = 0; j < 4; j++) qc[mt][nt][j] = 0.f;
        #pragma unroll
        for (int nt = 0; nt < 4; nt++) {
            const unsigned char* Wr = sm + SM_WQ + (nt * 8 + gid) * 80;
            unsigned bq[2][2];
            bq[0][0] = *(const unsigned*)(Wr + tig * 4);
            bq[0][1] = *(const unsigned*)(Wr + 16 + tig * 4);
            bq[1][0] = *(const unsigned*)(Wr + 32 + tig * 4);
            bq[1][1] = *(const unsigned*)(Wr + 48 + tig * 4);
            #pragma unroll
            for (int mt = 0; mt < 2; mt++) {
                mma16816(qc[mt][nt], xa[mt][0], bq[0]);
                mma16816(qc[mt][nt], xa[mt][1], bq[1]);
            }
            float b0 = sqbf[nt * 8 + tig * 2], b1 = sqbf[nt * 8 + tig * 2 + 1];
            #pragma unroll
            for (int mt = 0; mt < 2; mt++) {
                qc[mt][nt][0] += b0; qc[mt][nt][1] += b1;
                qc[mt][nt][2] += b0; qc[mt][nt][3] += b1;
            }
        }
        #pragma unroll
        for (int h = 0; h < 2; h++)
            #pragma unroll
            for (int mt = 0; mt < 2; mt++) {
                qf[h][mt][0] = packbf(qc[mt][2*h][0],   qc[mt][2*h][1]);
                qf[h][mt][1] = packbf(qc[mt][2*h][2],   qc[mt][2*h][3]);
                qf[h][mt][2] = packbf(qc[mt][2*h+1][0], qc[mt][2*h+1][1]);
                qf[h][mt][3] = packbf(qc[mt][2*h+1][2], qc[mt][2*h+1][3]);
            }
    }

    /* ---- Phase B: streaming softmax-attention.
       P via bf16 magic-exp (FFMA+PRMT, no F2I/CVT); row-sums via a third
       PV MMA against an all-ones B fragment (no FADDs, no shuffles).      */
    const unsigned ONES2 = 0x3F803F80u;          /* bf16x2 {1.0, 1.0} */
    unsigned vb1[2]; vb1[0] = ONES2; vb1[1] = ONES2;
    unsigned zf[2][2][4];   /* [mtile][ktile=head] Z A-fragments */
    #pragma unroll
    for (int h = 0; h < 2; h++) {
        const unsigned char* Kh = sm + SM_K + h * 12288;
        const unsigned char* Vh = sm + SM_V + h * 8448;
        float oa[2][2][4];      /* [mt][dt][j] */
        float osum[2][4];       /* [mt][j] : row sums via ones-MMA */
        #pragma unroll
        for (int mt = 0; mt < 2; mt++) {
            #pragma unroll
            for (int j = 0; j < 4; j++) { oa[mt][0][j] = 0.f; oa[mt][1][j] = 0.f; osum[mt][j] = 0.f; }
        }
        #pragma unroll 4
        for (int nt2 = 0; nt2 < 16; nt2++) {
            const int t0 = nt2 * 16;
            unsigned kb[2][2], vb[2][2];
            kb[0][0] = *(const unsigned*)(Kh + (t0 + gid) * 48 + tig * 4);
            kb[0][1] = *(const unsigned*)(Kh + (t0 + gid) * 48 + 16 + tig * 4);
            kb[1][0] = *(const unsigned*)(Kh + (t0 + 8 + gid) * 48 + tig * 4);
            kb[1][1] = *(const unsigned*)(Kh + (t0 + 8 + gid) * 48 + 16 + tig * 4);
            vb[0][0] = *(const unsigned*)(Vh + gid * 528 + t0 * 2 + tig * 4);
            vb[0][1] = *(const unsigned*)(Vh + gid * 528 + t0 * 2 + 16 + tig * 4);
            vb[1][0] = *(const unsigned*)(Vh + (8 + gid) * 528 + t0 * 2 + tig * 4);
            vb[1][1] = *(const unsigned*)(Vh + (8 + gid) * 528 + t0 * 2 + 16 + tig * 4);
            #pragma unroll
            for (int mt = 0; mt < 2; mt++) {
                float sc0[4] = {0.f,0.f,0.f,0.f}, sc1[4] = {0.f,0.f,0.f,0.f};
                mma16816(sc0, qf[h][mt], kb[0]);
                mma16816(sc1, qf[h][mt], kb[1]);
                unsigned pa[4];
                pa[0] = fexp2bf(sc0[0], sc0[1]);
                pa[1] = fexp2bf(sc0[2], sc0[3]);
                pa[2] = fexp2bf(sc1[0], sc1[1]);
                pa[3] = fexp2bf(sc1[2], sc1[3]);
                mma16816(oa[mt][0], pa, vb[0]);
                mma16816(oa[mt][1], pa, vb[1]);
                mma16816(osum[mt], pa, vb1);
            }
        }
        #pragma unroll
        for (int mt = 0; mt < 2; mt++) {
            float i0 = 1.f / osum[mt][0];
            float i1 = 1.f / osum[mt][2];
            zf[mt][h][0] = packbf(oa[mt][0][0] * i0, oa[mt][0][1] * i0);
            zf[mt][h][1] = packbf(oa[mt][0][2] * i1, oa[mt][0][3] * i1);
            zf[mt][h][2] = packbf(oa[mt][1][0] * i0, oa[mt][1][1] * i0);
            zf[mt][h][3] = packbf(oa[mt][1][2] * i1, oa[mt][1][3] * i1);
        }
    }

    /* ---- Phase C: Y = Z @ Wo^T ; residual, write, output-GN stats ---- */
    float gam = __ldg(gammap);
    float lsum = 0.f, lsq = 0.f;
    float* yb = y + (size_t)b * NTOT;
    #pragma unroll
    for (int nt = 0; nt < 4; nt++) {
        const unsigned char* Wr = sm + SM_WO + (nt * 8 + gid) * 80;
        unsigned bo[2][2];
        bo[0][0] = *(const unsigned*)(Wr + tig * 4);
        bo[0][1] = *(const unsigned*)(Wr + 16 + tig * 4);
        bo[1][0] = *(const unsigned*)(Wr + 32 + tig * 4);
        bo[1][1] = *(const unsigned*)(Wr + 48 + tig * 4);
        #pragma unroll
        for (int mt = 0; mt < 2; mt++) {
            float yc[4] = {0.f, 0.f, 0.f, 0.f};
            mma16816(yc, zf[mt][0], bo[0]);
            mma16816(yc, zf[mt][1], bo[1]);
            int ch = nt * 8 + tig * 2;
            int r0 = rabs[mt];
            size_t i00 = (size_t)ch * S_ + r0;
            size_t i01 = i00 + S_;
            float y00 = xb[i00]     + gam * yc[0];
            float y01 = xb[i01]     + gam * yc[1];
            float y10 = xb[i00 + 8] + gam * yc[2];
            float y11 = xb[i01 + 8] + gam * yc[3];
            yb[i00] = y00; yb[i01] = y01; yb[i00 + 8] = y10; yb[i01 + 8] = y11;
            lsum += (y00 + y01) + (y10 + y11);
            lsq  += (y00*y00 + y01*y01) + (y10*y10 + y11*y11);
        }
    }
    #pragma unroll
    for (int o = 16; o; o >>= 1) {
        lsum += __shfl_down_sync(0xffffffffu, lsum, o);
        lsq  += __shfl_down_sync(0xffffffffu, lsq,  o);
    }
    float* red = (float*)(sm + SM_RED);
    __syncthreads();
    if (lane == 0) { red[w] = lsum; red[4 + w] = lsq; }
    __syncthreads();
    if (tid == 0) {
        float ts = red[0] + red[1] + red[2] + red[3];
        float tq = red[4] + red[5] + red[6] + red[7];
        atomicAdd(&g_s2[b], (double)ts);
        atomicAdd(&g_q2[b], (double)tq);
    }
}

/* ===================== K4: output GroupNorm (exact-cover, MLP=4) ========== */
__global__ void k_final(float* __restrict__ out,
                        const float* __restrict__ gw, const float* __restrict__ gb) {
    int bc = blockIdx.y;
    int b = bc >> 5, c = bc & 31;
    double mean = g_s2[b] / (double)NTOT;
    double var  = g_q2[b] / (double)NTOT - mean * mean;
    float inv = (float)(1.0 / sqrt(var + 1e-5));
    float a  = gw[c] * inv;
    float bb = gb[c] - gw[c] * (float)mean * inv;
    float4* p = (float4*)(out + ((size_t)b * C_ + c) * S_);
    int j = blockIdx.x * 256 + threadIdx.x;     /* 0..12287 */
    float4 v0 = p[j], v1 = p[j + 12288], v2 = p[j + 24576], v3 = p[j + 36864];
    v0.x = a*v0.x + bb; v0.y = a*v0.y + bb; v0.z = a*v0.z + bb; v0.w = a*v0.w + bb;
    v1.x = a*v1.x + bb; v1.y = a*v1.y + bb; v1.z = a*v1.z + bb; v1.w = a*v1.w + bb;
    v2.x = a*v2.x + bb; v2.y = a*v2.y + bb; v2.z = a*v2.z + bb; v2.w = a*v2.w + bb;
    v3.x = a*v3.x + bb; v3.y = a*v3.y + bb; v3.z = a*v3.z + bb; v3.w = a*v3.w + bb;
    p[j] = v0; p[j + 12288] = v1; p[j + 24576] = v2; p[j + 36864] = v3;
}

/* ===================== launch ============================================= */
extern "C" void kernel_launch(void* const* d_in, const int* in_sizes, int n_in,
                              void* d_out, int out_size) {
    const float* cost  = (const float*)d_in[0];
    const float* feat  = (const float*)d_in[1];
    const float* Wq    = (const float*)d_in[2];
    const float* Wk    = (const float*)d_in[3];
    const float* Wv    = (const float*)d_in[4];
    const float* Wo    = (const float*)d_in[5];
    const float* gniw  = (const float*)d_in[6];
    const float* gnib  = (const float*)d_in[7];
    const float* gnow  = (const float*)d_in[8];
    const float* gnob  = (const float*)d_in[9];
    const float* gamma = (const float*)d_in[10];
    float* out = (float*)d_out;

    k_prep<<<dim3(64 + NRED, B_), 256>>>(feat, Wk, Wv, cost);
    k_fold<<<B_, 1024>>>(Wq, Wo, gniw, gnib);
    k_attn_mma<<<dim3(S_ / 128, B_), 128>>>(cost, gamma, out);
    k_final<<<dim3(48, B_ * C_), 256>>>(out, gnow, gnob);
}